// round 15
// baseline (speedup 1.0000x reference)
#include <cuda_runtime.h>
#include <cuda_fp16.h>
#include <math.h>

static constexpr int   NUM_MOVABLE = 1000000;
static constexpr int   NUM_NODES   = 1200000;
static constexpr int   NQ          = NUM_NODES / 4;      // 300000 quads
static constexpr int   NQ_MOV      = NUM_MOVABLE / 4;    // 250000 movable quads
static constexpr int   NB          = 512;
static constexpr int   MAP_SIZE    = NB * NB;
static constexpr float BS          = 1.953125f;          // 1000/512, exact fp32
static constexpr int   NBANK       = 64;
static constexpr int   BLK_PER_SM  = 4;
static constexpr int   NBLK        = 148 * BLK_PER_SM;   // 592, all co-resident
static constexpr int   NTHR        = 256;
static constexpr int   NT          = NBLK * NTHR;        // 151552 threads
// q0 = tid is ALWAYS movable (NT < NQ_MOV). q1 = tid+NT classification:
static constexpr int   Q1_MOV_LIM  = NQ_MOV - NT;        // 98448  (movable below)
static constexpr int   Q1_VAL_LIM  = NQ - NT;            // 148448 (filler below, invalid above)

// All 4 bilinear corners x {route,pin} as 8 x fp16 in ONE 16B entry.
__device__ uint4    g_quadh[MAP_SIZE];       // 4MB scratch
__device__ double   g_acc[5][NBANK];         // 0:old 1:inc 2:route_ex 3:pin_ex 4:filler
__device__ unsigned g_count = 0;             // barrier arrive counter (self-resetting)
__device__ volatile unsigned g_sense = 0;    // barrier sense (1 then back to 0)

__device__ __forceinline__ void grid_bar(unsigned target) {
    __syncthreads();
    if (threadIdx.x == 0) {
        __threadfence();
        if (atomicAdd(&g_count, 1u) == (unsigned)(NBLK - 1)) {
            g_count = 0u;
            __threadfence();
            g_sense = target;
        } else {
            while (g_sense != target) __nanosleep(64);
            __threadfence();
        }
    }
    __syncthreads();
}

__device__ __forceinline__ float fast_sqrt(float x) {
    float r; asm("sqrt.approx.f32 %0, %1;" : "=f"(r) : "f"(x)); return r;
}
__device__ __forceinline__ float fast_rcp(float x) {
    float r; asm("rcp.approx.f32 %0, %1;" : "=f"(r) : "f"(x)); return r;
}
__device__ __forceinline__ float route_clamp(float u) {
    float r = u * u * fast_sqrt(u);                        // u^2.5
    return fminf(fmaxf(r, 0.5f), 2.0f);
}
__device__ __forceinline__ float pin_clamp(float p) {
    return fminf(fmaxf(p, 0.4f), 2.5f);
}
__device__ __forceinline__ unsigned pack_h2(float a, float b) {
    __half2 h = __floats2half2_rn(a, b);
    return *(unsigned*)&h;
}

// Consume one node's stencil: weights from inputs, corners from pre-fetched v.
__device__ __forceinline__ void node_consume(float sx, float sy, float px, float py,
                                             uint4 v, float& ro, float& po, float& a) {
    a = sx * sy;
    float xh = px + sx, yh = py + sy;
    float blx0 = floorf(px / BS) * BS;
    float bly0 = floorf(py / BS) * BS;
    // node < bin size -> at most 2x2 bins; 3rd overlap exactly 0
    float ox0 = fmaxf(fminf(xh, blx0 + BS)       - fmaxf(px, blx0),      0.f);
    float ox1 = fmaxf(fminf(xh, blx0 + 2.f * BS) - fmaxf(px, blx0 + BS), 0.f);
    float oy0 = fmaxf(fminf(yh, bly0 + BS)       - fmaxf(py, bly0),      0.f);
    float oy1 = fmaxf(fminf(yh, bly0 + 2.f * BS) - fmaxf(py, bly0 + BS), 0.f);
    float2 c00 = __half22float2(*(__half2*)&v.x);
    float2 c01 = __half22float2(*(__half2*)&v.y);
    float2 c10 = __half22float2(*(__half2*)&v.z);
    float2 c11 = __half22float2(*(__half2*)&v.w);
    float w00 = ox0 * oy0, w01 = ox0 * oy1, w10 = ox1 * oy0, w11 = ox1 * oy1;
    ro = w00 * c00.x + w01 * c01.x + w10 * c10.x + w11 * c11.x;
    po = w00 * c00.y + w01 * c01.y + w10 * c10.y + w11 * c11.y;
}

__device__ __forceinline__ int stencil_idx(float px, float py) {
    return (int)floorf(px / BS) * NB + (int)floorf(py / BS);
}

__global__ void __launch_bounds__(NTHR, BLK_PER_SM)
k_fused(const float4* __restrict__ posx, const float4* __restrict__ posy,
        const float4* __restrict__ nsx,  const float4* __restrict__ nsy,
        const float* __restrict__ route, const float* __restrict__ pin,
        float4* __restrict__ out) {
    const int tid = blockIdx.x * NTHR + threadIdx.x;
    const int q0  = tid;
    const int q1  = tid + NT;
    const int q1c = (q1 < NQ) ? q1 : q0;                   // safe in-bounds clamp
    const bool q1mov = tid < Q1_MOV_LIM;
    const bool q1fil = (tid >= Q1_MOV_LIM) && (tid < Q1_VAL_LIM);

    // ---------------- Phase 0: build fp16 stencil table + zero acc --------
    if (tid < 5 * NBANK) ((double*)g_acc)[tid] = 0.0;
    for (int e = tid; e < MAP_SIZE; e += NT) {             // <=2 entries/thread
        int bx = e >> 9, by = e & (NB - 1);
        int bx1 = min(bx + 1, NB - 1), by1 = min(by + 1, NB - 1);
        int i00 = bx * NB + by,  i01 = bx * NB + by1;
        int i10 = bx1 * NB + by, i11 = bx1 * NB + by1;
        uint4 v;
        v.x = pack_h2(route_clamp(__ldg(&route[i00])), pin_clamp(__ldg(&pin[i00])));
        v.y = pack_h2(route_clamp(__ldg(&route[i01])), pin_clamp(__ldg(&pin[i01])));
        v.z = pack_h2(route_clamp(__ldg(&route[i10])), pin_clamp(__ldg(&pin[i10])));
        v.w = pack_h2(route_clamp(__ldg(&route[i11])), pin_clamp(__ldg(&pin[i11])));
        g_quadh[e] = v;
    }

    grid_bar(1u);   // table + zeroed accumulators visible grid-wide

    // ---------------- Phase 1: 8-wide load pipeline + banked reductions ---
    // Load ALL inputs, issue ALL stencil gathers, THEN consume: MLP 4 -> 8+.
    float inc0[4], inc1[4];
    float v_old = 0.f, v_inc = 0.f, v_re = 0.f, v_pe = 0.f, v_f = 0.f;
    {
        float sx0[4], sy0[4], px0[4], py0[4];
        float sx1[4], sy1[4], px1[4], py1[4];
        *(float4*)sx0 = nsx[q0];   *(float4*)sy0 = nsy[q0];
        *(float4*)px0 = posx[q0];  *(float4*)py0 = posy[q0];
        *(float4*)sx1 = nsx[q1c];  *(float4*)sy1 = nsy[q1c];
        *(float4*)px1 = posx[q1c]; *(float4*)py1 = posy[q1c];

        uint4 v0[4], v1[4];
        #pragma unroll
        for (int j = 0; j < 4; j++) v0[j] = __ldg(&g_quadh[stencil_idx(px0[j], py0[j])]);
        if (q1mov) {
            #pragma unroll
            for (int j = 0; j < 4; j++) v1[j] = __ldg(&g_quadh[stencil_idx(px1[j], py1[j])]);
        }

        #pragma unroll
        for (int j = 0; j < 4; j++) {                      // q0: always movable
            float ro, po, a;
            node_consume(sx0[j], sy0[j], px0[j], py0[j], v0[j], ro, po, a);
            float ai = fmaxf(fmaxf(ro, po) - a, 0.f);
            inc0[j] = ai;
            v_old += a; v_inc += ai;
            v_re += fmaxf(ro - a, 0.f); v_pe += fmaxf(po - a, 0.f);
        }
        if (q1mov) {
            #pragma unroll
            for (int j = 0; j < 4; j++) {
                float ro, po, a;
                node_consume(sx1[j], sy1[j], px1[j], py1[j], v1[j], ro, po, a);
                float ai = fmaxf(fmaxf(ro, po) - a, 0.f);
                inc1[j] = ai;
                v_old += a; v_inc += ai;
                v_re += fmaxf(ro - a, 0.f); v_pe += fmaxf(po - a, 0.f);
            }
        } else if (q1fil) {
            #pragma unroll
            for (int j = 0; j < 4; j++) v_f += sx1[j] * sy1[j];
        }
    }
    // block reduce 5 accumulators
    #pragma unroll
    for (int off = 16; off; off >>= 1) {
        v_old += __shfl_down_sync(0xffffffffu, v_old, off);
        v_inc += __shfl_down_sync(0xffffffffu, v_inc, off);
        v_re  += __shfl_down_sync(0xffffffffu, v_re , off);
        v_pe  += __shfl_down_sync(0xffffffffu, v_pe , off);
        v_f   += __shfl_down_sync(0xffffffffu, v_f  , off);
    }
    __shared__ float sm[5][8];
    {
        int w = threadIdx.x >> 5, l = threadIdx.x & 31;
        if (l == 0) { sm[0][w] = v_old; sm[1][w] = v_inc; sm[2][w] = v_re; sm[3][w] = v_pe; sm[4][w] = v_f; }
    }
    __syncthreads();
    if (threadIdx.x == 0) {
        int bank = blockIdx.x & (NBANK - 1);
        #pragma unroll
        for (int j = 0; j < 5; j++) {
            float s = 0.f;
            #pragma unroll
            for (int k = 0; k < 8; k++) s += sm[j][k];
            atomicAdd(&g_acc[j][bank], (double)s);
        }
    }

    // Hoisted phase-2 reloads: independent of the global scalars; the barrier
    // wait hides their (L1-hit) latency. Live-set here is small -> no spills.
    float sx0[4], sy0[4], px0[4], py0[4];
    float sx1[4], sy1[4], px1[4], py1[4];
    *(float4*)sx0 = nsx[q0];   *(float4*)sy0 = nsy[q0];
    *(float4*)px0 = posx[q0];  *(float4*)py0 = posy[q0];
    *(float4*)sx1 = nsx[q1c];  *(float4*)sy1 = nsy[q1c];
    *(float4*)px1 = posx[q1c]; *(float4*)py1 = posy[q1c];

    grid_bar(0u);   // all partial sums landed; sense back to initial value

    // ---------------- Phase 2: scalars (per block) + apply + write --------
    __shared__ float s_sc[4];   // 0:adjust 1:scale 2:fcond 3:fratio
    if (threadIdx.x < 32) {
        int l = threadIdx.x;
        double t0 = g_acc[0][l] + g_acc[0][l + 32];
        double t1 = g_acc[1][l] + g_acc[1][l + 32];
        double t2 = g_acc[2][l] + g_acc[2][l + 32];
        double t3 = g_acc[3][l] + g_acc[3][l + 32];
        double t4 = g_acc[4][l] + g_acc[4][l + 32];
        #pragma unroll
        for (int off = 16; off; off >>= 1) {
            t0 += __shfl_down_sync(0xffffffffu, t0, off);
            t1 += __shfl_down_sync(0xffffffffu, t1, off);
            t2 += __shfl_down_sync(0xffffffffu, t2, off);
            t3 += __shfl_down_sync(0xffffffffu, t3, off);
            t4 += __shfl_down_sync(0xffffffffu, t4, off);
        }
        if (l == 0) {
            float old_sum = (float)t0, inc_sum = (float)t1;
            float re = (float)t2, pe = (float)t3, fsum = (float)t4;
            float budget    = fminf(0.1f * 500000.0f, 1000000.0f - old_sum);
            float raw_scale = budget / inc_sum;
            float scale     = fminf(fmaxf(raw_scale, 0.f), 1.f);
            float inc_eff   = (raw_scale <= 0.f) ? 0.f : inc_sum * scale;
            float new_sum   = old_sum + inc_eff;
            bool route_flag = (re / old_sum) > 0.01f;
            bool pin_flag   = (pe / old_sum) > 0.05f;
            bool adjust = ((inc_eff / old_sum) > 0.01f) && (route_flag || pin_flag);
            bool fcond  = adjust && (new_sum + fsum > 1000000.0f);
            s_sc[0] = adjust ? 1.f : 0.f;
            s_sc[1] = scale;
            s_sc[2] = fcond ? 1.f : 0.f;
            s_sc[3] = sqrtf(fmaxf(1000000.0f - new_sum, 0.f) / fsum);
        }
    }
    __syncthreads();
    const float adjust = s_sc[0], scale = s_sc[1], fcond = s_sc[2], fratio = s_sc[3];

    // q0: always movable, data already in registers.
    {
        float nxA[4], nyA[4], qxA[4], qyA[4];
        #pragma unroll
        for (int j = 0; j < 4; j++) {
            float sx = sx0[j], sy = sy0[j];
            float nx = sx, ny = sy, qx = px0[j], qy = py0[j];
            if (adjust != 0.f) {
                float a  = sx * sy;
                float na = a + inc0[j] * scale;
                float mr = fast_sqrt(na * fast_rcp(a));
                nx = sx * mr; ny = sy * mr;
                qx = px0[j] + 0.5f * (sx - nx);
                qy = py0[j] + 0.5f * (sy - ny);
            }
            nxA[j] = nx; nyA[j] = ny; qxA[j] = qx; qyA[j] = qy;
        }
        out[q0]          = *(const float4*)qxA;
        out[NQ + q0]     = *(const float4*)qyA;
        out[2 * NQ + q0] = *(const float4*)nxA;
        out[3 * NQ + q0] = *(const float4*)nyA;
    }
    // q1: movable or filler (skip if invalid), data in registers.
    if (q1 < NQ) {
        float nxA[4], nyA[4], qxA[4], qyA[4];
        if (q1mov) {
            #pragma unroll
            for (int j = 0; j < 4; j++) {
                float sx = sx1[j], sy = sy1[j];
                float nx = sx, ny = sy, qx = px1[j], qy = py1[j];
                if (adjust != 0.f) {
                    float a  = sx * sy;
                    float na = a + inc1[j] * scale;
                    float mr = fast_sqrt(na * fast_rcp(a));
                    nx = sx * mr; ny = sy * mr;
                    qx = px1[j] + 0.5f * (sx - nx);
                    qy = py1[j] + 0.5f * (sy - ny);
                }
                nxA[j] = nx; nyA[j] = ny; qxA[j] = qx; qyA[j] = qy;
            }
        } else {
            #pragma unroll
            for (int j = 0; j < 4; j++) {
                float sx = sx1[j], sy = sy1[j];
                float nx = sx, ny = sy, qx = px1[j], qy = py1[j];
                if (fcond != 0.f) {
                    nx = sx * fratio; ny = sy * fratio;
                    qx = px1[j] + 0.5f * (sx - nx);
                    qy = py1[j] + 0.5f * (sy - ny);
                }
                nxA[j] = nx; nyA[j] = ny; qxA[j] = qx; qyA[j] = qy;
            }
        }
        out[q1]          = *(const float4*)qxA;
        out[NQ + q1]     = *(const float4*)qyA;
        out[2 * NQ + q1] = *(const float4*)nxA;
        out[3 * NQ + q1] = *(const float4*)nyA;
    }
}

// ----------------------------------------------------------------
extern "C" void kernel_launch(void* const* d_in, const int* in_sizes, int n_in,
                              void* d_out, int out_size) {
    const float* pos   = (const float*)d_in[0];
    const float* nsx   = (const float*)d_in[1];
    const float* nsy   = (const float*)d_in[2];
    const float* route = (const float*)d_in[6];
    const float* pin   = (const float*)d_in[7];

    k_fused<<<NBLK, NTHR>>>((const float4*)pos,
                            (const float4*)(pos + NUM_NODES),
                            (const float4*)nsx,
                            (const float4*)nsy,
                            route, pin,
                            (float4*)d_out);
}

// round 16
// speedup vs baseline: 1.2076x; 1.2076x over previous
#include <cuda_runtime.h>
#include <cuda_fp16.h>
#include <math.h>

static constexpr int   NUM_MOVABLE = 1000000;
static constexpr int   NUM_NODES   = 1200000;
static constexpr int   NQ          = NUM_NODES / 4;      // 300000 quads
static constexpr int   NQ_MOV      = NUM_MOVABLE / 4;    // 250000 movable quads
static constexpr int   NB          = 512;
static constexpr int   MAP_SIZE    = NB * NB;
static constexpr float BS          = 1.953125f;          // 1000/512, exact fp32
static constexpr float INV_BS      = 0.512f;             // 1/BS (node<bin ⇒ off-by-one safe)
static constexpr int   NBANK       = 64;
static constexpr int   BLK_PER_SM  = 4;
static constexpr int   NBLK        = 148 * BLK_PER_SM;   // 592, all co-resident
static constexpr int   NTHR        = 256;
static constexpr int   NT          = NBLK * NTHR;        // 151552 threads
// q0 = tid is ALWAYS movable (NT < NQ_MOV). q1 = tid+NT classification:
static constexpr int   Q1_MOV_LIM  = NQ_MOV - NT;        // 98448  (movable below)
static constexpr int   Q1_VAL_LIM  = NQ - NT;            // 148448 (filler below, invalid above)

// All 4 bilinear corners x {route,pin} as 8 x fp16 in ONE 16B entry.
__device__ uint4    g_quadh[MAP_SIZE];       // 4MB scratch
__device__ double   g_acc[5][NBANK];         // 0:old 1:inc 2:route_ex 3:pin_ex 4:filler
__device__ unsigned g_count = 0;             // barrier arrive counter (self-resetting)
__device__ volatile unsigned g_sense = 0;    // barrier sense (1 then back to 0)

__device__ __forceinline__ void grid_bar(unsigned target) {
    __syncthreads();
    if (threadIdx.x == 0) {
        __threadfence();
        if (atomicAdd(&g_count, 1u) == (unsigned)(NBLK - 1)) {
            g_count = 0u;
            __threadfence();
            g_sense = target;
        } else {
            while (g_sense != target) __nanosleep(64);
            __threadfence();
        }
    }
    __syncthreads();
}

__device__ __forceinline__ float fast_sqrt(float x) {
    float r; asm("sqrt.approx.f32 %0, %1;" : "=f"(r) : "f"(x)); return r;
}
__device__ __forceinline__ float fast_rcp(float x) {
    float r; asm("rcp.approx.f32 %0, %1;" : "=f"(r) : "f"(x)); return r;
}
__device__ __forceinline__ float route_clamp(float u) {
    float r = u * u * fast_sqrt(u);                        // u^2.5
    return fminf(fmaxf(r, 0.5f), 2.0f);
}
__device__ __forceinline__ float pin_clamp(float p) {
    return fminf(fmaxf(p, 0.4f), 2.5f);
}
__device__ __forceinline__ unsigned pack_h2(float a, float b) {
    __half2 h = __floats2half2_rn(a, b);
    return *(unsigned*)&h;
}

// Per-node stencil: index via mul+cvt.rd (no IEEE div); gather launches early.
__device__ __forceinline__ void node_area(float sx, float sy, float px, float py,
                                          float& ro, float& po, float& a) {
    a = sx * sy;
    float xh = px + sx, yh = py + sy;
    int bx0 = __float2int_rd(px * INV_BS);
    int by0 = __float2int_rd(py * INV_BS);
    uint4 v = __ldg(&g_quadh[bx0 * NB + by0]);             // ONE gather: whole stencil
    float blx0 = bx0 * BS, bly0 = by0 * BS;
    // node < bin size -> at most 2x2 bins; 3rd overlap exactly 0
    float ox0 = fmaxf(fminf(xh, blx0 + BS)       - fmaxf(px, blx0),      0.f);
    float ox1 = fmaxf(fminf(xh, blx0 + 2.f * BS) - fmaxf(px, blx0 + BS), 0.f);
    float oy0 = fmaxf(fminf(yh, bly0 + BS)       - fmaxf(py, bly0),      0.f);
    float oy1 = fmaxf(fminf(yh, bly0 + 2.f * BS) - fmaxf(py, bly0 + BS), 0.f);
    float2 c00 = __half22float2(*(__half2*)&v.x);
    float2 c01 = __half22float2(*(__half2*)&v.y);
    float2 c10 = __half22float2(*(__half2*)&v.z);
    float2 c11 = __half22float2(*(__half2*)&v.w);
    float w00 = ox0 * oy0, w01 = ox0 * oy1, w10 = ox1 * oy0, w11 = ox1 * oy1;
    ro = w00 * c00.x + w01 * c01.x + w10 * c10.x + w11 * c11.x;
    po = w00 * c00.y + w01 * c01.y + w10 * c10.y + w11 * c11.y;
}

__global__ void __launch_bounds__(NTHR, BLK_PER_SM)
k_fused(const float4* __restrict__ posx, const float4* __restrict__ posy,
        const float4* __restrict__ nsx,  const float4* __restrict__ nsy,
        const float* __restrict__ route, const float* __restrict__ pin,
        float4* __restrict__ out) {
    const int tid = blockIdx.x * NTHR + threadIdx.x;
    const int q0  = tid;
    const int q1  = tid + NT;
    const int q1c = (q1 < NQ) ? q1 : q0;                   // safe in-bounds clamp
    const bool q1mov = tid < Q1_MOV_LIM;
    const bool q1fil = (tid >= Q1_MOV_LIM) && (tid < Q1_VAL_LIM);

    // ---------------- Phase 0: build fp16 stencil table + zero acc --------
    if (tid < 5 * NBANK) ((double*)g_acc)[tid] = 0.0;
    for (int e = tid; e < MAP_SIZE; e += NT) {             // <=2 entries/thread
        int bx = e >> 9, by = e & (NB - 1);
        int bx1 = min(bx + 1, NB - 1), by1 = min(by + 1, NB - 1);
        int i00 = bx * NB + by,  i01 = bx * NB + by1;
        int i10 = bx1 * NB + by, i11 = bx1 * NB + by1;
        uint4 v;
        v.x = pack_h2(route_clamp(__ldg(&route[i00])), pin_clamp(__ldg(&pin[i00])));
        v.y = pack_h2(route_clamp(__ldg(&route[i01])), pin_clamp(__ldg(&pin[i01])));
        v.z = pack_h2(route_clamp(__ldg(&route[i10])), pin_clamp(__ldg(&pin[i10])));
        v.w = pack_h2(route_clamp(__ldg(&route[i11])), pin_clamp(__ldg(&pin[i11])));
        g_quadh[e] = v;
    }

    grid_bar(1u);   // table + zeroed accumulators visible grid-wide

    // ---------------- Phase 1: per-node areas + banked reductions ---------
    float inc0[4], inc1[4];
    float v_old = 0.f, v_inc = 0.f, v_re = 0.f, v_pe = 0.f, v_f = 0.f;
    {   // q0: always movable
        float sxA[4], syA[4], pxA[4], pyA[4];
        *(float4*)sxA = nsx[q0];  *(float4*)syA = nsy[q0];
        *(float4*)pxA = posx[q0]; *(float4*)pyA = posy[q0];
        #pragma unroll
        for (int j = 0; j < 4; j++) {
            float ro, po, a;
            node_area(sxA[j], syA[j], pxA[j], pyA[j], ro, po, a);
            float ai = fmaxf(fmaxf(ro, po) - a, 0.f);
            inc0[j] = ai;
            v_old += a; v_inc += ai;
            v_re += fmaxf(ro - a, 0.f); v_pe += fmaxf(po - a, 0.f);
        }
    }
    {   // q1: movable / filler / skip
        float sxA[4], syA[4], pxA[4], pyA[4];
        *(float4*)sxA = nsx[q1c]; *(float4*)syA = nsy[q1c];
        if (q1mov) {
            *(float4*)pxA = posx[q1c]; *(float4*)pyA = posy[q1c];
            #pragma unroll
            for (int j = 0; j < 4; j++) {
                float ro, po, a;
                node_area(sxA[j], syA[j], pxA[j], pyA[j], ro, po, a);
                float ai = fmaxf(fmaxf(ro, po) - a, 0.f);
                inc1[j] = ai;
                v_old += a; v_inc += ai;
                v_re += fmaxf(ro - a, 0.f); v_pe += fmaxf(po - a, 0.f);
            }
        } else if (q1fil) {
            #pragma unroll
            for (int j = 0; j < 4; j++) v_f += sxA[j] * syA[j];
        }
    }
    // block reduce 5 accumulators
    #pragma unroll
    for (int off = 16; off; off >>= 1) {
        v_old += __shfl_down_sync(0xffffffffu, v_old, off);
        v_inc += __shfl_down_sync(0xffffffffu, v_inc, off);
        v_re  += __shfl_down_sync(0xffffffffu, v_re , off);
        v_pe  += __shfl_down_sync(0xffffffffu, v_pe , off);
        v_f   += __shfl_down_sync(0xffffffffu, v_f  , off);
    }
    __shared__ float sm[5][8];
    {
        int w = threadIdx.x >> 5, l = threadIdx.x & 31;
        if (l == 0) { sm[0][w] = v_old; sm[1][w] = v_inc; sm[2][w] = v_re; sm[3][w] = v_pe; sm[4][w] = v_f; }
    }
    __syncthreads();
    if (threadIdx.x == 0) {
        int bank = blockIdx.x & (NBANK - 1);
        #pragma unroll
        for (int j = 0; j < 5; j++) {
            float s = 0.f;
            #pragma unroll
            for (int k = 0; k < 8; k++) s += sm[j][k];
            atomicAdd(&g_acc[j][bank], (double)s);
        }
    }

    // Hoisted phase-2 reloads: independent of the global scalars; the barrier
    // wait hides their (L1-hit) latency. Live-set here is small -> no spills.
    float sx0[4], sy0[4], px0[4], py0[4];
    float sx1[4], sy1[4], px1[4], py1[4];
    *(float4*)sx0 = nsx[q0];   *(float4*)sy0 = nsy[q0];
    *(float4*)px0 = posx[q0];  *(float4*)py0 = posy[q0];
    *(float4*)sx1 = nsx[q1c];  *(float4*)sy1 = nsy[q1c];
    *(float4*)px1 = posx[q1c]; *(float4*)py1 = posy[q1c];

    grid_bar(0u);   // all partial sums landed; sense back to initial value

    // ---------------- Phase 2: scalars (per block) + apply + write --------
    __shared__ float s_sc[4];   // 0:adjust 1:scale 2:fcond 3:fratio
    if (threadIdx.x < 32) {
        int l = threadIdx.x;
        double t0 = g_acc[0][l] + g_acc[0][l + 32];
        double t1 = g_acc[1][l] + g_acc[1][l + 32];
        double t2 = g_acc[2][l] + g_acc[2][l + 32];
        double t3 = g_acc[3][l] + g_acc[3][l + 32];
        double t4 = g_acc[4][l] + g_acc[4][l + 32];
        #pragma unroll
        for (int off = 16; off; off >>= 1) {
            t0 += __shfl_down_sync(0xffffffffu, t0, off);
            t1 += __shfl_down_sync(0xffffffffu, t1, off);
            t2 += __shfl_down_sync(0xffffffffu, t2, off);
            t3 += __shfl_down_sync(0xffffffffu, t3, off);
            t4 += __shfl_down_sync(0xffffffffu, t4, off);
        }
        if (l == 0) {
            float old_sum = (float)t0, inc_sum = (float)t1;
            float re = (float)t2, pe = (float)t3, fsum = (float)t4;
            float budget    = fminf(0.1f * 500000.0f, 1000000.0f - old_sum);
            float raw_scale = budget / inc_sum;
            float scale     = fminf(fmaxf(raw_scale, 0.f), 1.f);
            float inc_eff   = (raw_scale <= 0.f) ? 0.f : inc_sum * scale;
            float new_sum   = old_sum + inc_eff;
            bool route_flag = (re / old_sum) > 0.01f;
            bool pin_flag   = (pe / old_sum) > 0.05f;
            bool adjust = ((inc_eff / old_sum) > 0.01f) && (route_flag || pin_flag);
            bool fcond  = adjust && (new_sum + fsum > 1000000.0f);
            s_sc[0] = adjust ? 1.f : 0.f;
            s_sc[1] = scale;
            s_sc[2] = fcond ? 1.f : 0.f;
            s_sc[3] = sqrtf(fmaxf(1000000.0f - new_sum, 0.f) / fsum);
        }
    }
    __syncthreads();
    const float adjust = s_sc[0], scale = s_sc[1], fcond = s_sc[2], fratio = s_sc[3];

    // q0: always movable, data already in registers.
    {
        float nxA[4], nyA[4], qxA[4], qyA[4];
        #pragma unroll
        for (int j = 0; j < 4; j++) {
            float sx = sx0[j], sy = sy0[j];
            float nx = sx, ny = sy, qx = px0[j], qy = py0[j];
            if (adjust != 0.f) {
                float a  = sx * sy;
                float na = a + inc0[j] * scale;
                float mr = fast_sqrt(na * fast_rcp(a));
                nx = sx * mr; ny = sy * mr;
                qx = px0[j] + 0.5f * (sx - nx);
                qy = py0[j] + 0.5f * (sy - ny);
            }
            nxA[j] = nx; nyA[j] = ny; qxA[j] = qx; qyA[j] = qy;
        }
        out[q0]          = *(const float4*)qxA;
        out[NQ + q0]     = *(const float4*)qyA;
        out[2 * NQ + q0] = *(const float4*)nxA;
        out[3 * NQ + q0] = *(const float4*)nyA;
    }
    // q1: movable or filler (skip if invalid), data in registers.
    if (q1 < NQ) {
        float nxA[4], nyA[4], qxA[4], qyA[4];
        if (q1mov) {
            #pragma unroll
            for (int j = 0; j < 4; j++) {
                float sx = sx1[j], sy = sy1[j];
                float nx = sx, ny = sy, qx = px1[j], qy = py1[j];
                if (adjust != 0.f) {
                    float a  = sx * sy;
                    float na = a + inc1[j] * scale;
                    float mr = fast_sqrt(na * fast_rcp(a));
                    nx = sx * mr; ny = sy * mr;
                    qx = px1[j] + 0.5f * (sx - nx);
                    qy = py1[j] + 0.5f * (sy - ny);
                }
                nxA[j] = nx; nyA[j] = ny; qxA[j] = qx; qyA[j] = qy;
            }
        } else {
            #pragma unroll
            for (int j = 0; j < 4; j++) {
                float sx = sx1[j], sy = sy1[j];
                float nx = sx, ny = sy, qx = px1[j], qy = py1[j];
                if (fcond != 0.f) {
                    nx = sx * fratio; ny = sy * fratio;
                    qx = px1[j] + 0.5f * (sx - nx);
                    qy = py1[j] + 0.5f * (sy - ny);
                }
                nxA[j] = nx; nyA[j] = ny; qxA[j] = qx; qyA[j] = qy;
            }
        }
        out[q1]          = *(const float4*)qxA;
        out[NQ + q1]     = *(const float4*)qyA;
        out[2 * NQ + q1] = *(const float4*)nxA;
        out[3 * NQ + q1] = *(const float4*)nyA;
    }
}

// ----------------------------------------------------------------
extern "C" void kernel_launch(void* const* d_in, const int* in_sizes, int n_in,
                              void* d_out, int out_size) {
    const float* pos   = (const float*)d_in[0];
    const float* nsx   = (const float*)d_in[1];
    const float* nsy   = (const float*)d_in[2];
    const float* route = (const float*)d_in[6];
    const float* pin   = (const float*)d_in[7];

    k_fused<<<NBLK, NTHR>>>((const float4*)pos,
                            (const float4*)(pos + NUM_NODES),
                            (const float4*)nsx,
                            (const float4*)nsy,
                            route, pin,
                            (float4*)d_out);
}